// round 16
// baseline (speedup 1.0000x reference)
#include <cuda_runtime.h>
#include <cstdint>

#define D_IN     256
#define A_ATT    128
#define W_WIN    64
#define T_LEN    4096
#define B_BATCH  32
#define TCW      512     // t-chunk for window kernel
#define HALO     63
#define M_TILE   128     // rows per gate tile
#define XROWW    136     // gate x row pad (floats): 544 B -> conflict-free LDS.64

// gate scratch: B*T floats = 512 KB (device global, allocation-free)
__device__ float g_gate[B_BATCH * T_LEN];

// ---------------------------------------------------------------------------
// helpers
// ---------------------------------------------------------------------------
__device__ __forceinline__ uint32_t smem_u32(const void* p) {
    uint32_t a;
    asm("{ .reg .u64 t; cvta.to.shared.u64 t, %1; cvt.u32.u64 %0, t; }" : "=r"(a) : "l"(p));
    return a;
}
__device__ __forceinline__ float tanh_fast(float v) {
    float y; asm("tanh.approx.f32 %0, %1;" : "=f"(y) : "f"(v)); return y;
}
// pack two fp32 -> f16x2 (lo = first arg)
__device__ __forceinline__ uint32_t f2h2(float lo, float hi) {
    uint32_t u;
    asm("cvt.rn.f16x2.f32 %0, %1, %2;" : "=r"(u) : "f"(hi), "f"(lo));
    return u;
}
__device__ __forceinline__ void mma_f16(float* c, const uint32_t* a, const uint32_t* b) {
    asm volatile("mma.sync.aligned.m16n8k16.row.col.f32.f16.f16.f32 "
                 "{%0,%1,%2,%3}, {%4,%5,%6,%7}, {%8,%9}, {%0,%1,%2,%3};"
                 : "+f"(c[0]), "+f"(c[1]), "+f"(c[2]), "+f"(c[3])
                 : "r"(a[0]), "r"(a[1]), "r"(a[2]), "r"(a[3]), "r"(b[0]), "r"(b[1]));
}
__device__ __forceinline__ void mbar_wait_parity(uint32_t mbar, uint32_t parity) {
    uint32_t done;
    asm volatile("{\n\t.reg .pred p;\n\t"
                 "mbarrier.try_wait.parity.shared::cta.b64 p, [%1], %2;\n\t"
                 "selp.b32 %0, 1, 0, p;\n\t}"
                 : "=r"(done) : "r"(mbar), "r"(parity) : "memory");
    if (!done) {
        asm volatile("{\n\t.reg .pred P1;\n\t"
                     "WL_%=:\n\t"
                     "mbarrier.try_wait.parity.shared::cta.b64 P1, [%0], %1, 0x989680;\n\t"
                     "@P1 bra.uni WD_%=;\n\t"
                     "bra.uni WL_%=;\n\t"
                     "WD_%=:\n\t}" :: "r"(mbar), "r"(parity) : "memory");
    }
}

// ---------------------------------------------------------------------------
// Gate kernel (R12/R15 config — unchanged, best measured ~38-40us)
// SMEM: Wph 67584 | x bufs 2x69632 | bw 1024 | red 2048 | mbar 16
// ---------------------------------------------------------------------------
#define SM_WPH   0
#define SM_X0    67584
#define SM_X1    137216
#define SM_BW    206848
#define SM_RED   207872
#define SM_MBAR  209920
#define SM_TOT   210048

__global__ void __launch_bounds__(512, 1) gate_kernel(
    const float* __restrict__ x, const float* __restrict__ Wp,
    const float* __restrict__ bp, const float* __restrict__ Wg, int ntiles)
{
    extern __shared__ char smem[];
    uint32_t*     wph = (uint32_t*)(smem + SM_WPH);
    const float*  xsf[2] = { (const float*)(smem + SM_X0), (const float*)(smem + SM_X1) };
    float2*       bwv = (float2*)(smem + SM_BW);
    float*        red = (float*)(smem + SM_RED);

    const int tid = threadIdx.x, wid = tid >> 5, lane = tid & 31;
    const int lane4 = lane >> 2, lanek = lane & 3;
    const int wm = wid & 3, wn = wid >> 2;

    const uint32_t sbase  = smem_u32(smem);
    const uint32_t mbar_u = sbase + SM_MBAR;
    const uint32_t xs_u[2] = { sbase + SM_X0, sbase + SM_X1 };

    if (tid == 0) {
        asm volatile("mbarrier.init.shared.b64 [%0], 1;" :: "r"(mbar_u)     : "memory");
        asm volatile("mbarrier.init.shared.b64 [%0], 1;" :: "r"(mbar_u + 8) : "memory");
    }

    for (int i = tid; i < 128 * 128; i += 512) {
        const int n = i >> 7, j = i & 127;
        const float v0 = Wp[n * D_IN + 2 * j];
        const float v1 = Wp[n * D_IN + 2 * j + 1];
        wph[n * 132 + j] = f2h2(v0, v1);
    }
    if (tid < 128) { float2 bw; bw.x = bp[tid]; bw.y = Wg[tid]; bwv[tid] = bw; }
    __syncthreads();

    auto issue_q = [&](int q) {
        const int buf = q & 1;
        if (tid == 0)
            asm volatile("mbarrier.arrive.expect_tx.shared::cta.b64 _, [%0], %1;"
                         :: "r"(mbar_u + buf * 8), "r"(65536u) : "memory");
        if (tid < 128) {
            const int tile = blockIdx.x + (q >> 1) * gridDim.x;
            const float* src = x + (size_t)tile * M_TILE * D_IN
                                 + (size_t)tid * D_IN + (q & 1) * 128;
            const uint32_t dst = xs_u[buf] + tid * (XROWW * 4);
            asm volatile(
                "cp.async.bulk.shared::cta.global.mbarrier::complete_tx::bytes "
                "[%0], [%1], 512, [%2];"
                :: "r"(dst), "l"(src), "r"(mbar_u + buf * 8) : "memory");
        }
    };

    int xrow[2][2];
    #pragma unroll
    for (int mt = 0; mt < 2; mt++)
        #pragma unroll
        for (int rh = 0; rh < 2; rh++)
            xrow[mt][rh] = (wm * 32 + mt * 16 + rh * 8 + lane4) * XROWW;
    int bn32[4];
    #pragma unroll
    for (int nt = 0; nt < 4; nt++) bn32[nt] = (wn * 32 + nt * 8 + lane4) * 132;

    auto compute_half = [&](const float* xb, int kh32, float (&acc)[2][4][4]) {
        #pragma unroll
        for (int ks = 0; ks < 8; ks++) {
            const int k0 = ks * 16;
            uint32_t a[2][4];
            #pragma unroll
            for (int mt = 0; mt < 2; mt++)
                #pragma unroll
                for (int rh = 0; rh < 2; rh++) {
                    const float2 p = *(const float2*)&xb[xrow[mt][rh] + k0 + 2 * lanek];
                    const float2 q = *(const float2*)&xb[xrow[mt][rh] + k0 + 8 + 2 * lanek];
                    a[mt][rh]     = f2h2(p.x, p.y);
                    a[mt][2 + rh] = f2h2(q.x, q.y);
                }
            uint32_t b[4][2];
            #pragma unroll
            for (int nt = 0; nt < 4; nt++) {
                b[nt][0] = wph[bn32[nt] + kh32 + k0 / 2 + lanek];
                b[nt][1] = wph[bn32[nt] + kh32 + k0 / 2 + 4 + lanek];
            }
            #pragma unroll
            for (int mt = 0; mt < 2; mt++)
                #pragma unroll
                for (int nt = 0; nt < 4; nt++)
                    mma_f16(acc[mt][nt], a[mt], b[nt]);
        }
    };

    const int iters = (ntiles - (int)blockIdx.x + (int)gridDim.x - 1) / (int)gridDim.x;
    const int nq = iters * 2;
    if (nq <= 0) return;

    issue_q(0);
    if (nq > 1) issue_q(1);

    float acc[2][4][4];
    #pragma unroll
    for (int mt = 0; mt < 2; mt++)
        #pragma unroll
        for (int nt = 0; nt < 4; nt++)
            #pragma unroll
            for (int c = 0; c < 4; c++) acc[mt][nt][c] = 0.f;

    for (int q = 0; q < nq; q++) {
        mbar_wait_parity(mbar_u + (q & 1) * 8, (uint32_t)((q >> 1) & 1));
        compute_half(xsf[q & 1], (q & 1) * 64, acc);
        __syncthreads();
        if (q + 2 < nq) issue_q(q + 2);

        if (q & 1) {
            const int tile = blockIdx.x + (q >> 1) * gridDim.x;
            float s[2][2] = {{0.f, 0.f}, {0.f, 0.f}};
            #pragma unroll
            for (int mt = 0; mt < 2; mt++)
                #pragma unroll
                for (int nt = 0; nt < 4; nt++) {
                    const int colb = wn * 32 + nt * 8 + 2 * lanek;
                    const float2 bw0 = bwv[colb], bw1 = bwv[colb + 1];
                    s[mt][0] = fmaf(bw0.y, tanh_fast(acc[mt][nt][0] + bw0.x),
                               fmaf(bw1.y, tanh_fast(acc[mt][nt][1] + bw1.x), s[mt][0]));
                    s[mt][1] = fmaf(bw0.y, tanh_fast(acc[mt][nt][2] + bw0.x),
                               fmaf(bw1.y, tanh_fast(acc[mt][nt][3] + bw1.x), s[mt][1]));
                }
            #pragma unroll
            for (int off = 1; off <= 2; off <<= 1) {
                #pragma unroll
                for (int mt = 0; mt < 2; mt++) {
                    s[mt][0] += __shfl_xor_sync(0xffffffffu, s[mt][0], off);
                    s[mt][1] += __shfl_xor_sync(0xffffffffu, s[mt][1], off);
                }
            }
            if (lanek == 0) {
                #pragma unroll
                for (int mt = 0; mt < 2; mt++)
                    #pragma unroll
                    for (int rh = 0; rh < 2; rh++)
                        red[wn * 128 + wm * 32 + mt * 16 + rh * 8 + lane4] = s[mt][rh];
            }
            __syncthreads();
            if (tid < 128) {
                const float t = red[tid] + red[128 + tid] + red[256 + tid] + red[384 + tid];
                g_gate[tile * M_TILE + tid] = 1.f / (1.f + __expf(-t));
            }
            #pragma unroll
            for (int mt = 0; mt < 2; mt++)
                #pragma unroll
                for (int nt = 0; nt < 4; nt++)
                    #pragma unroll
                    for (int c = 0; c < 4; c++) acc[mt][nt][c] = 0.f;
        }
    }
}

// ---------------------------------------------------------------------------
// Stage B: sliding causal window, window=64 — SMEM-staged version.
// Block = (b, 64-ch quarter, 512-t chunk). Stage [t0-63, t0+512] x 64ch fp32
// into SMEM once (x read 1.12x from DRAM total), then all add/sub/prefill
// reads are LDS. Thread = (tsub 0..15 x 32 t, dg 0..15 float4).
// SMEM: xs 576 x 256B = 147456 | gs 2304 | rinv 2048  -> 151808 B, 1 CTA/SM.
// ---------------------------------------------------------------------------
#define WSM_XS    0
#define WSM_GS    147456
#define WSM_RINV  149760
#define WSM_TOT   151808

__global__ void __launch_bounds__(256, 1) window_kernel(
    const float* __restrict__ x, float* __restrict__ out)
{
    extern __shared__ char wsm[];
    float* xs   = (float*)(wsm + WSM_XS);      // [576][64]
    float* gs   = (float*)(wsm + WSM_GS);      // [575]
    float* rinv = (float*)(wsm + WSM_RINV);    // [512]

    const int b   = blockIdx.z;
    const int dq  = blockIdx.y;                 // channel quarter (64 ch)
    const int t0  = blockIdx.x * TCW;
    const int tid = threadIdx.x;
    const int tsub = tid >> 4;                  // 0..15
    const int dg   = tid & 15;                  // float4 within quarter

    const float* xq = x + ((size_t)b * T_LEN) * D_IN + dq * 64;

    // ---- stage x [t0-63 .. t0+512] x 64ch into smem (batch-6 float4) ----
    // 576 rows x 16 float4 = 9216 items = 256 threads x 36
    #pragma unroll 1
    for (int jb = 0; jb < 36; jb += 6) {
        float4 v[6]; int ridx[6];
        #pragma unroll
        for (int u = 0; u < 6; u++) {
            const int idx = tid + (jb + u) * 256;
            const int row = idx >> 4, c4 = idx & 15;
            int t = t0 - HALO + row;
            t = t < 0 ? 0 : (t > T_LEN - 1 ? T_LEN - 1 : t);
            v[u] = *(const float4*)(xq + (size_t)t * D_IN + c4 * 4);
            ridx[u] = row * 64 + c4 * 4;
        }
        #pragma unroll
        for (int u = 0; u < 6; u++)
            *(float4*)(xs + ridx[u]) = v[u];
    }
    // gs: 575 values
    for (int i = tid; i < TCW + HALO; i += 256) {
        const int t = t0 - HALO + i;
        gs[i] = (t >= 0) ? g_gate[b * T_LEN + t] : 0.f;
    }
    __syncthreads();

    {   // rinv: den for output i = sum gs[i .. i+63]; thread owns 2 consecutive
        const int i0 = tid * 2;
        float den = 0.f;
        #pragma unroll 8
        for (int j = 0; j < W_WIN; j++) den += gs[i0 + j];
        rinv[i0] = __frcp_rn(den);
        den += gs[i0 + W_WIN] - gs[i0];
        rinv[i0 + 1] = __frcp_rn(den);
    }
    __syncthreads();

    // ---- window pass: all x reads from smem ----
    const int ts0 = t0 + tsub * 32;            // first output t for this thread
    const int rb  = tsub * 32;                  // smem row of t = ts0-63
    const int gb  = tsub * 32;                  // gs[gb+j] = g(ts0-63+j)
    float4* ob = (float4*)(out + ((size_t)b * T_LEN) * D_IN) + dq * 16 + dg;
    const int S = D_IN / 4;

    float4 num = make_float4(0.f, 0.f, 0.f, 0.f);

    // prefill [ts0-63, ts0-1]: rows rb..rb+62 in smem (j==63 masked)
    #pragma unroll 1
    for (int j0 = 0; j0 < W_WIN; j0 += 4) {
        #pragma unroll
        for (int u = 0; u < 4; u++) {
            const int j = j0 + u;
            const float4 xa = *(const float4*)(xs + (rb + j) * 64 + dg * 4);
            const float gv = (j < W_WIN - 1) ? gs[gb + j] : 0.f;
            num.x = fmaf(gv, xa.x, num.x);
            num.y = fmaf(gv, xa.y, num.y);
            num.z = fmaf(gv, xa.z, num.z);
            num.w = fmaf(gv, xa.w, num.w);
        }
    }

    // main: 32 outputs; add row = rb+63+j, sub row = rb+j
    #pragma unroll 1
    for (int j0 = 0; j0 < 32; j0 += 4) {
        #pragma unroll
        for (int u = 0; u < 4; u++) {
            const int j = j0 + u;
            const float4 xa = *(const float4*)(xs + (rb + HALO + j) * 64 + dg * 4);
            const float ga = gs[gb + HALO + j];
            num.x = fmaf(ga, xa.x, num.x);
            num.y = fmaf(ga, xa.y, num.y);
            num.z = fmaf(ga, xa.z, num.z);
            num.w = fmaf(ga, xa.w, num.w);
            const float r = rinv[tsub * 32 + j];
            float4 o;
            o.x = num.x * r; o.y = num.y * r; o.z = num.z * r; o.w = num.w * r;
            ob[(size_t)(ts0 + j) * S] = o;
            const float4 xsu = *(const float4*)(xs + (rb + j) * 64 + dg * 4);
            const float gr = gs[gb + j];       // 0 when t-63 < 0
            num.x = fmaf(-gr, xsu.x, num.x);
            num.y = fmaf(-gr, xsu.y, num.y);
            num.z = fmaf(-gr, xsu.z, num.z);
            num.w = fmaf(-gr, xsu.w, num.w);
        }
    }
}

// ---------------------------------------------------------------------------
extern "C" void kernel_launch(void* const* d_in, const int* in_sizes, int n_in,
                              void* d_out, int out_size)
{
    const float* x  = (const float*)d_in[0];
    const float* Wp = (const float*)d_in[1];
    const float* bp = (const float*)d_in[2];
    const float* Wg = (const float*)d_in[3];
    float* out = (float*)d_out;

    const int rows_total = in_sizes[0] / D_IN;   // B*T
    const int ntiles = rows_total / M_TILE;      // 1024
    const int batches = rows_total / T_LEN;      // 32

    int nsm = 148;
    cudaDeviceGetAttribute(&nsm, cudaDevAttrMultiProcessorCount, 0);
    const int grid = nsm < ntiles ? nsm : ntiles;

    cudaFuncSetAttribute(gate_kernel,
                         cudaFuncAttributeMaxDynamicSharedMemorySize, SM_TOT);
    gate_kernel<<<grid, 512, SM_TOT>>>(x, Wp, bp, Wg, ntiles);

    cudaFuncSetAttribute(window_kernel,
                         cudaFuncAttributeMaxDynamicSharedMemorySize, WSM_TOT);
    dim3 wgrid(T_LEN / TCW, D_IN / 64, batches);
    window_kernel<<<wgrid, 256, WSM_TOT>>>(x, out);
}

// round 17
// speedup vs baseline: 1.2545x; 1.2545x over previous
#include <cuda_runtime.h>
#include <cstdint>

#define D_IN     256
#define A_ATT    128
#define W_WIN    64
#define T_LEN    4096
#define B_BATCH  32
#define TC       1024    // t-chunk for window kernel
#define M_TILE   128     // rows per gate tile
#define XROWW    136     // x row pad (floats): 544 B; 136%32==8 -> conflict-free LDS.64

// gate scratch: B*T floats = 512 KB (device global, allocation-free)
__device__ float g_gate[B_BATCH * T_LEN];

// ---------------------------------------------------------------------------
// helpers
// ---------------------------------------------------------------------------
__device__ __forceinline__ uint32_t smem_u32(const void* p) {
    uint32_t a;
    asm("{ .reg .u64 t; cvta.to.shared.u64 t, %1; cvt.u32.u64 %0, t; }" : "=r"(a) : "l"(p));
    return a;
}
__device__ __forceinline__ float tanh_fast(float v) {
    float y; asm("tanh.approx.f32 %0, %1;" : "=f"(y) : "f"(v)); return y;
}
// pack two fp32 -> f16x2 (lo = first arg)
__device__ __forceinline__ uint32_t f2h2(float lo, float hi) {
    uint32_t u;
    asm("cvt.rn.f16x2.f32 %0, %1, %2;" : "=r"(u) : "f"(hi), "f"(lo));
    return u;
}
__device__ __forceinline__ void mma_f16(float* c, const uint32_t* a, const uint32_t* b) {
    asm volatile("mma.sync.aligned.m16n8k16.row.col.f32.f16.f16.f32 "
                 "{%0,%1,%2,%3}, {%4,%5,%6,%7}, {%8,%9}, {%0,%1,%2,%3};"
                 : "+f"(c[0]), "+f"(c[1]), "+f"(c[2]), "+f"(c[3])
                 : "r"(a[0]), "r"(a[1]), "r"(a[2]), "r"(a[3]), "r"(b[0]), "r"(b[1]));
}
__device__ __forceinline__ void mbar_wait_parity(uint32_t mbar, uint32_t parity) {
    uint32_t done;
    asm volatile("{\n\t.reg .pred p;\n\t"
                 "mbarrier.try_wait.parity.shared::cta.b64 p, [%1], %2;\n\t"
                 "selp.b32 %0, 1, 0, p;\n\t}"
                 : "=r"(done) : "r"(mbar), "r"(parity) : "memory");
    if (!done) {
        asm volatile("{\n\t.reg .pred P1;\n\t"
                     "WL_%=:\n\t"
                     "mbarrier.try_wait.parity.shared::cta.b64 P1, [%0], %1, 0x989680;\n\t"
                     "@P1 bra.uni WD_%=;\n\t"
                     "bra.uni WL_%=;\n\t"
                     "WD_%=:\n\t}" :: "r"(mbar), "r"(parity) : "memory");
    }
}

// ---------------------------------------------------------------------------
// SMEM layout (dynamic, bytes) for gate kernel:
//  Wph 128x264 halves = 67584 | x bufs 2 x (128 rows x 544 B) = 139264
//  | bw 1024 | red 2048 | mbar 16
// ---------------------------------------------------------------------------
#define SM_WPH   0
#define SM_X0    67584
#define SM_X1    137216     // 67584 + 69632
#define SM_BW    206848
#define SM_RED   207872
#define SM_MBAR  209920
#define SM_TOT   210048

__global__ void __launch_bounds__(512, 1) gate_kernel(
    const float* __restrict__ x, const float* __restrict__ Wp,
    const float* __restrict__ bp, const float* __restrict__ Wg, int ntiles)
{
    extern __shared__ char smem[];
    uint32_t*     wph = (uint32_t*)(smem + SM_WPH);   // u32 = half2; row stride 132 u32
    const float*  xsf[2] = { (const float*)(smem + SM_X0), (const float*)(smem + SM_X1) };
    float2*       bwv = (float2*)(smem + SM_BW);
    float*        red = (float*)(smem + SM_RED);

    const int tid = threadIdx.x, wid = tid >> 5, lane = tid & 31;
    const int lane4 = lane >> 2, lanek = lane & 3;
    const int wm = wid & 3, wn = wid >> 2;          // 4 x 4 warp grid

    const uint32_t sbase  = smem_u32(smem);
    const uint32_t mbar_u = sbase + SM_MBAR;
    const uint32_t xs_u[2] = { sbase + SM_X0, sbase + SM_X1 };

    if (tid == 0) {
        asm volatile("mbarrier.init.shared.b64 [%0], 1;" :: "r"(mbar_u)     : "memory");
        asm volatile("mbarrier.init.shared.b64 [%0], 1;" :: "r"(mbar_u + 8) : "memory");
    }

    // stage Wp -> fp16 (rn), half-pairs; row n stride 132 u32 (264 halves)
    for (int i = tid; i < 128 * 128; i += 512) {
        const int n = i >> 7, j = i & 127;          // j = k/2
        const float v0 = Wp[n * D_IN + 2 * j];
        const float v1 = Wp[n * D_IN + 2 * j + 1];
        wph[n * 132 + j] = f2h2(v0, v1);
    }
    if (tid < 128) { float2 bw; bw.x = bp[tid]; bw.y = Wg[tid]; bwv[tid] = bw; }
    __syncthreads();   // Wph + mbar init visible

    // q = half index: tile q>>1, K-half q&1, buffer q&1.
    // 128 row-bulks of 512 B each; expect_tx = 65536.
    auto issue_q = [&](int q) {
        const int buf = q & 1;
        if (tid == 0)
            asm volatile("mbarrier.arrive.expect_tx.shared::cta.b64 _, [%0], %1;"
                         :: "r"(mbar_u + buf * 8), "r"(65536u) : "memory");
        if (tid < 128) {
            const int tile = blockIdx.x + (q >> 1) * gridDim.x;
            const float* src = x + (size_t)tile * M_TILE * D_IN
                                 + (size_t)tid * D_IN + (q & 1) * 128;
            const uint32_t dst = xs_u[buf] + tid * (XROWW * 4);
            asm volatile(
                "cp.async.bulk.shared::cta.global.mbarrier::complete_tx::bytes "
                "[%0], [%1], 512, [%2];"
                :: "r"(dst), "l"(src), "r"(mbar_u + buf * 8) : "memory");
        }
    };

    // per-thread fragment bases
    int xrow[2][2];
    #pragma unroll
    for (int mt = 0; mt < 2; mt++)
        #pragma unroll
        for (int rh = 0; rh < 2; rh++)
            xrow[mt][rh] = (wm * 32 + mt * 16 + rh * 8 + lane4) * XROWW;
    int bn32[4];
    #pragma unroll
    for (int nt = 0; nt < 4; nt++) bn32[nt] = (wn * 32 + nt * 8 + lane4) * 132;

    // one K-half (128 k = 8 ksteps of 16); kh32 = half * 64 (u32 offset in wph)
    auto compute_half = [&](const float* xb, int kh32, float (&acc)[2][4][4]) {
        #pragma unroll
        for (int ks = 0; ks < 8; ks++) {
            const int k0 = ks * 16;
            uint32_t a[2][4];
            #pragma unroll
            for (int mt = 0; mt < 2; mt++)
                #pragma unroll
                for (int rh = 0; rh < 2; rh++) {
                    const float2 p = *(const float2*)&xb[xrow[mt][rh] + k0 + 2 * lanek];
                    const float2 q = *(const float2*)&xb[xrow[mt][rh] + k0 + 8 + 2 * lanek];
                    a[mt][rh]     = f2h2(p.x, p.y);
                    a[mt][2 + rh] = f2h2(q.x, q.y);
                }
            uint32_t b[4][2];
            #pragma unroll
            for (int nt = 0; nt < 4; nt++) {
                b[nt][0] = wph[bn32[nt] + kh32 + k0 / 2 + lanek];
                b[nt][1] = wph[bn32[nt] + kh32 + k0 / 2 + 4 + lanek];
            }
            #pragma unroll
            for (int mt = 0; mt < 2; mt++)
                #pragma unroll
                for (int nt = 0; nt < 4; nt++)
                    mma_f16(acc[mt][nt], a[mt], b[nt]);
        }
    };

    const int iters = (ntiles - (int)blockIdx.x + (int)gridDim.x - 1) / (int)gridDim.x;
    const int nq = iters * 2;
    if (nq <= 0) return;

    issue_q(0);
    if (nq > 1) issue_q(1);

    float acc[2][4][4];
    #pragma unroll
    for (int mt = 0; mt < 2; mt++)
        #pragma unroll
        for (int nt = 0; nt < 4; nt++)
            #pragma unroll
            for (int c = 0; c < 4; c++) acc[mt][nt][c] = 0.f;

    for (int q = 0; q < nq; q++) {
        mbar_wait_parity(mbar_u + (q & 1) * 8, (uint32_t)((q >> 1) & 1));
        compute_half(xsf[q & 1], (q & 1) * 64, acc);
        __syncthreads();                  // all reads of buf done before refill
        if (q + 2 < nq) issue_q(q + 2);

        if (q & 1) {
            const int tile = blockIdx.x + (q >> 1) * gridDim.x;
            float s[2][2] = {{0.f, 0.f}, {0.f, 0.f}};
            #pragma unroll
            for (int mt = 0; mt < 2; mt++)
                #pragma unroll
                for (int nt = 0; nt < 4; nt++) {
                    const int colb = wn * 32 + nt * 8 + 2 * lanek;
                    const float2 bw0 = bwv[colb], bw1 = bwv[colb + 1];
                    s[mt][0] = fmaf(bw0.y, tanh_fast(acc[mt][nt][0] + bw0.x),
                               fmaf(bw1.y, tanh_fast(acc[mt][nt][1] + bw1.x), s[mt][0]));
                    s[mt][1] = fmaf(bw0.y, tanh_fast(acc[mt][nt][2] + bw0.x),
                               fmaf(bw1.y, tanh_fast(acc[mt][nt][3] + bw1.x), s[mt][1]));
                }
            #pragma unroll
            for (int off = 1; off <= 2; off <<= 1) {
                #pragma unroll
                for (int mt = 0; mt < 2; mt++) {
                    s[mt][0] += __shfl_xor_sync(0xffffffffu, s[mt][0], off);
                    s[mt][1] += __shfl_xor_sync(0xffffffffu, s[mt][1], off);
                }
            }
            if (lanek == 0) {
                #pragma unroll
                for (int mt = 0; mt < 2; mt++)
                    #pragma unroll
                    for (int rh = 0; rh < 2; rh++)
                        red[wn * 128 + wm * 32 + mt * 16 + rh * 8 + lane4] = s[mt][rh];
            }
            __syncthreads();
            if (tid < 128) {
                const float t = red[tid] + red[128 + tid] + red[256 + tid] + red[384 + tid];
                g_gate[tile * M_TILE + tid] = 1.f / (1.f + __expf(-t));
            }
            // reset accumulators (thread-private; next red write is beyond the
            // next half's post-compute __syncthreads -> trailing sync removed)
            #pragma unroll
            for (int mt = 0; mt < 2; mt++)
                #pragma unroll
                for (int nt = 0; nt < 4; nt++)
                    #pragma unroll
                    for (int c = 0; c < 4; c++) acc[mt][nt][c] = 0.f;
        }
    }
}

// ---------------------------------------------------------------------------
// Stage B: sliding causal window, window=64.  (R6/R12 version — best measured)
// Block = (b, 64-channel quarter, t-chunk 1024). Thread = (dg 0..15 float4,
// tsub 0..15 each owning 64 consecutive t).
// ---------------------------------------------------------------------------
__global__ void __launch_bounds__(256, 4) window_kernel(
    const float* __restrict__ x, float* __restrict__ out)
{
    const int b   = blockIdx.z;
    const int dq  = blockIdx.y;                 // channel quarter (64 ch)
    const int t0  = blockIdx.x * TC;
    const int tid = threadIdx.x;
    const int tsub = tid >> 4;                  // 0..15
    const int dg   = tid & 15;                  // float4 within quarter

    __shared__ float gs[TC + W_WIN - 1];        // g[t0-63 .. t0+TC-1]; 0 for t<0
    __shared__ float rinv[TC];
    for (int i = tid; i < TC + W_WIN - 1; i += 256) {
        const int t = t0 - (W_WIN - 1) + i;
        gs[i] = (t >= 0) ? g_gate[b * T_LEN + t] : 0.f;
    }
    __syncthreads();
    {
        const int i0 = tid * 4;
        float den = 0.f;
        #pragma unroll 8
        for (int j = 0; j < W_WIN; j++) den += gs[i0 + j];
        rinv[i0] = __frcp_rn(den);
        #pragma unroll
        for (int u = 1; u < 4; u++) {
            den += gs[i0 + W_WIN - 1 + u] - gs[i0 + u - 1];
            rinv[i0 + u] = __frcp_rn(den);
        }
    }
    __syncthreads();

    const int ts0 = t0 + tsub * 64;
    const int gb  = tsub * 64;
    const int S = D_IN / 4;
    const float4* xb = (const float4*)(x   + ((size_t)b * T_LEN) * D_IN) + dq * 16 + dg;
    float4*       ob = (float4*)      (out + ((size_t)b * T_LEN) * D_IN) + dq * 16 + dg;

    float4 num = make_float4(0.f, 0.f, 0.f, 0.f);

    #pragma unroll 1
    for (int j0 = 0; j0 < W_WIN; j0 += 4) {
        float4 xa[4]; float gv[4];
        #pragma unroll
        for (int u = 0; u < 4; u++) {
            const int j = j0 + u;
            const int t = ts0 - (W_WIN - 1) + j;
            const int tc = t < 0 ? 0 : t;
            xa[u] = xb[(size_t)tc * S];
            gv[u] = (j < W_WIN - 1) ? gs[gb + j] : 0.f;
        }
        #pragma unroll
        for (int u = 0; u < 4; u++) {
            num.x = fmaf(gv[u], xa[u].x, num.x);
            num.y = fmaf(gv[u], xa[u].y, num.y);
            num.z = fmaf(gv[u], xa[u].z, num.z);
            num.w = fmaf(gv[u], xa[u].w, num.w);
        }
    }

    #pragma unroll 1
    for (int j0 = 0; j0 < 64; j0 += 4) {
        float4 xa[4], xs[4];
        #pragma unroll
        for (int u = 0; u < 4; u++)
            xa[u] = xb[(size_t)(ts0 + j0 + u) * S];
        #pragma unroll
        for (int u = 0; u < 4; u++) {
            const int tr = ts0 + j0 + u - (W_WIN - 1);
            const int trc = tr < 0 ? 0 : tr;
            xs[u] = xb[(size_t)trc * S];
        }
        #pragma unroll
        for (int u = 0; u < 4; u++) {
            const int j = j0 + u;
            const float ga = gs[gb + (W_WIN - 1) + j];
            num.x = fmaf(ga, xa[u].x, num.x);
            num.y = fmaf(ga, xa[u].y, num.y);
            num.z = fmaf(ga, xa[u].z, num.z);
            num.w = fmaf(ga, xa[u].w, num.w);
            const float r = rinv[gb + j];
            float4 o;
            o.x = num.x * r; o.y = num.y * r; o.z = num.z * r; o.w = num.w * r;
            ob[(size_t)(ts0 + j) * S] = o;
            const float gr = gs[gb + j];
            num.x = fmaf(-gr, xs[u].x, num.x);
            num.y = fmaf(-gr, xs[u].y, num.y);
            num.z = fmaf(-gr, xs[u].z, num.z);
            num.w = fmaf(-gr, xs[u].w, num.w);
        }
    }
}

// ---------------------------------------------------------------------------
extern "C" void kernel_launch(void* const* d_in, const int* in_sizes, int n_in,
                              void* d_out, int out_size)
{
    const float* x  = (const float*)d_in[0];
    const float* Wp = (const float*)d_in[1];
    const float* bp = (const float*)d_in[2];
    const float* Wg = (const float*)d_in[3];
    float* out = (float*)d_out;

    const int rows_total = in_sizes[0] / D_IN;   // B*T
    const int ntiles = rows_total / M_TILE;      // 1024
    const int batches = rows_total / T_LEN;      // 32

    int nsm = 148;
    cudaDeviceGetAttribute(&nsm, cudaDevAttrMultiProcessorCount, 0);
    const int grid = nsm < ntiles ? nsm : ntiles;

    cudaFuncSetAttribute(gate_kernel,
                         cudaFuncAttributeMaxDynamicSharedMemorySize, SM_TOT);
    gate_kernel<<<grid, 512, SM_TOT>>>(x, Wp, bp, Wg, ntiles);

    dim3 wgrid(T_LEN / TC, D_IN / 64, batches);
    window_kernel<<<wgrid, 256>>>(x, out);
}